// round 3
// baseline (speedup 1.0000x reference)
#include <cuda_runtime.h>

// ---------------------------------------------------------------------------
// Scratch (static __device__ globals — no allocation allowed)
// ---------------------------------------------------------------------------
#define NCAP 1000000
#define NWORDS 31250          // ceil(NCAP/32) bitmap words
#define FPAD 8                // padded feature stride (32B rows, one L2 sector)

__device__ float d_m[NCAP * FPAD];     // pool messages, stride 8 (32B-aligned rows)
__device__ float d_agg[NCAP * FPAD];   // segment-max accumulator, stride 8
__device__ float d_h1[NCAP * 5];       // sigmoid(conv1 output)
__device__ unsigned d_leafbm[NWORDS];  // leaf-node bitmap (128KB, L1/L2 resident)

__device__ __forceinline__ float sigm(float x) {
    return 1.0f / (1.0f + __expf(-x));
}

// ---------------------------------------------------------------------------
// Kernel: m1 = relu(x @ p1_W + p1_b); agg = 0; bitmap = 0
// ---------------------------------------------------------------------------
__global__ void node1_kernel(const float* __restrict__ x,
                             const float* __restrict__ W,
                             const float* __restrict__ b,
                             int N) {
    int i = blockIdx.x * blockDim.x + threadIdx.x;
    if (i < NWORDS) d_leafbm[i] = 0u;
    if (i >= N) return;
    float xv[5], m[5];
#pragma unroll
    for (int k = 0; k < 5; k++) xv[k] = x[i * 5 + k];
#pragma unroll
    for (int f = 0; f < 5; f++) {
        float acc = b[f];
#pragma unroll
        for (int k = 0; k < 5; k++) acc = fmaf(xv[k], W[k * 5 + f], acc);
        m[f] = fmaxf(acc, 0.0f);
    }
    float4* m4 = reinterpret_cast<float4*>(d_m) + (size_t)i * 2;
    m4[0] = make_float4(m[0], m[1], m[2], m[3]);
    m4[1] = make_float4(m[4], 0.0f, 0.0f, 0.0f);
    float4 z4 = make_float4(0.0f, 0.0f, 0.0f, 0.0f);
    float4* a4 = reinterpret_cast<float4*>(d_agg) + (size_t)i * 2;
    a4[0] = z4;
    a4[1] = z4;
}

// ---------------------------------------------------------------------------
// Kernel: set leaf bits
// ---------------------------------------------------------------------------
__global__ void leafset_kernel(const int* __restrict__ leaf, int L) {
    int j = blockIdx.x * blockDim.x + threadIdx.x;
    if (j >= L) return;
    int n = leaf[j];
    atomicOr(&d_leafbm[n >> 5], 1u << (n & 31));
}

// ---------------------------------------------------------------------------
// Edge scatter-max, feature-parallel: 5 lanes per edge, 6 edges per warp.
// All 5 lanes of an edge hit the SAME 32B sector for gather and for check
// -> 1 L1 wavefront per edge instead of many divergent ones.
// relu output >= 0 so signed-int atomicMax on the float bits is exact;
// stale (smaller) check reads are safe because agg values only grow.
// FILTER: skip edges whose dst is not a leaf (layer 2 only).
// ---------------------------------------------------------------------------
template <bool FILTER>
__global__ void edge_kernel(const int* __restrict__ src,
                            const int* __restrict__ dst,
                            int E) {
    int t = blockIdx.x * blockDim.x + threadIdx.x;
    int w = t >> 5;
    int lane = t & 31;
    int sub = lane / 5;                 // 0..6 (sub==6 -> lanes 30,31 idle)
    int f = lane - sub * 5;
    if (sub >= 6) return;
    int e = w * 6 + sub;
    if (e >= E) return;
    int d = dst[e];
    if (FILTER) {
        unsigned bm = d_leafbm[d >> 5];
        if (!((bm >> (d & 31)) & 1u)) return;
    }
    int s = src[e];
    int vb = __float_as_int(d_m[(size_t)s * FPAD + f]);
    if (vb > 0) {
        int* ag = reinterpret_cast<int*>(d_agg) + (size_t)d * FPAD + f;
        int cur = *ag;                  // possibly stale (<= current) -> safe filter
        if (vb > cur) atomicMax(ag, vb);
    }
}

// ---------------------------------------------------------------------------
// Kernel: h1 = sigmoid(x @ s1_W + agg1 @ n1_W + b1)
//         m2 = relu(h1 @ p2_W + p2_b); agg = 0 (reused for layer 2)
// ---------------------------------------------------------------------------
__global__ void node2_kernel(const float* __restrict__ x,
                             const float* __restrict__ s1W,
                             const float* __restrict__ n1W,
                             const float* __restrict__ b1,
                             const float* __restrict__ p2W,
                             const float* __restrict__ p2b,
                             int N) {
    int i = blockIdx.x * blockDim.x + threadIdx.x;
    if (i >= N) return;
    float xv[5], av[5], h[5], m[5];
#pragma unroll
    for (int k = 0; k < 5; k++) xv[k] = x[i * 5 + k];
    const float4* a4c = reinterpret_cast<const float4*>(d_agg) + (size_t)i * 2;
    float4 a0 = a4c[0];
    av[0] = a0.x; av[1] = a0.y; av[2] = a0.z; av[3] = a0.w;
    av[4] = d_agg[(size_t)i * FPAD + 4];
#pragma unroll
    for (int f = 0; f < 5; f++) {
        float acc = b1[f];
#pragma unroll
        for (int k = 0; k < 5; k++) acc = fmaf(xv[k], s1W[k * 5 + f], acc);
#pragma unroll
        for (int k = 0; k < 5; k++) acc = fmaf(av[k], n1W[k * 5 + f], acc);
        h[f] = sigm(acc);
        d_h1[(size_t)i * 5 + f] = h[f];
    }
#pragma unroll
    for (int f = 0; f < 5; f++) {
        float acc = p2b[f];
#pragma unroll
        for (int k = 0; k < 5; k++) acc = fmaf(h[k], p2W[k * 5 + f], acc);
        m[f] = fmaxf(acc, 0.0f);
    }
    float4* m4 = reinterpret_cast<float4*>(d_m) + (size_t)i * 2;
    m4[0] = make_float4(m[0], m[1], m[2], m[3]);
    m4[1] = make_float4(m[4], 0.0f, 0.0f, 0.0f);
    float4 z4 = make_float4(0.0f, 0.0f, 0.0f, 0.0f);
    float4* a4 = reinterpret_cast<float4*>(d_agg) + (size_t)i * 2;
    a4[0] = z4;
    a4[1] = z4;
}

// ---------------------------------------------------------------------------
// Kernel: leaf-only conv2 output + command product + 4-layer sigmoid MLP
// ---------------------------------------------------------------------------
__global__ __launch_bounds__(256) void leaf_kernel(
    const int* __restrict__ leaf, const float* __restrict__ cmd,
    const float* __restrict__ s2W, const float* __restrict__ n2W,
    const float* __restrict__ b2,
    const float* __restrict__ cmdW, const float* __restrict__ cmdb,
    const float* __restrict__ o1W, const float* __restrict__ o1b,
    const float* __restrict__ o2W, const float* __restrict__ o2b,
    const float* __restrict__ o3W, const float* __restrict__ o3b,
    const float* __restrict__ o4W, const float* __restrict__ o4b,
    float* __restrict__ out, int L) {

    __shared__ float S_s2W[50], S_n2W[50], S_b2[10], S_enc[10];
    __shared__ float S_o1W[320], S_o1b[32];
    __shared__ float S_o2W[1024], S_o2b[32];
    __shared__ float S_o3W[1024], S_o3b[32];
    __shared__ float S_o4W[32], S_o4b;

    int t = threadIdx.x;
    for (int k = t; k < 50; k += 256) { S_s2W[k] = s2W[k]; S_n2W[k] = n2W[k]; }
    for (int k = t; k < 320; k += 256) S_o1W[k] = o1W[k];
    for (int k = t; k < 1024; k += 256) { S_o2W[k] = o2W[k]; S_o3W[k] = o3W[k]; }
    if (t < 32) { S_o1b[t] = o1b[t]; S_o2b[t] = o2b[t]; S_o3b[t] = o3b[t]; S_o4W[t] = o4W[t]; }
    if (t < 10) {
        S_b2[t] = b2[t];
        S_enc[t] = cmdb[t] + cmd[0] * cmdW[t] + cmd[1] * cmdW[10 + t];
    }
    if (t == 0) S_o4b = o4b[0];
    __syncthreads();

    int j = blockIdx.x * 256 + t;
    if (j >= L) return;
    int node = leaf[j];

    float hv[5], av[5];
#pragma unroll
    for (int k = 0; k < 5; k++) hv[k] = d_h1[(size_t)node * 5 + k];
    const float4* a4c = reinterpret_cast<const float4*>(d_agg) + (size_t)node * 2;
    float4 a0 = a4c[0];
    av[0] = a0.x; av[1] = a0.y; av[2] = a0.z; av[3] = a0.w;
    av[4] = d_agg[(size_t)node * FPAD + 4];

    float p[10];
#pragma unroll
    for (int f = 0; f < 10; f++) {
        float acc = S_b2[f];
#pragma unroll
        for (int k = 0; k < 5; k++) acc = fmaf(hv[k], S_s2W[k * 10 + f], acc);
#pragma unroll
        for (int k = 0; k < 5; k++) acc = fmaf(av[k], S_n2W[k * 10 + f], acc);
        p[f] = acc * S_enc[f];
    }

    float z[32], z2[32];
#pragma unroll
    for (int f = 0; f < 32; f++) {
        float acc = S_o1b[f];
#pragma unroll
        for (int k = 0; k < 10; k++) acc = fmaf(p[k], S_o1W[k * 32 + f], acc);
        z[f] = sigm(acc);
    }
#pragma unroll
    for (int f = 0; f < 32; f++) {
        float acc = S_o2b[f];
#pragma unroll
        for (int k = 0; k < 32; k++) acc = fmaf(z[k], S_o2W[k * 32 + f], acc);
        z2[f] = sigm(acc);
    }
#pragma unroll
    for (int f = 0; f < 32; f++) {
        float acc = S_o3b[f];
#pragma unroll
        for (int k = 0; k < 32; k++) acc = fmaf(z2[k], S_o3W[k * 32 + f], acc);
        z[f] = sigm(acc);
    }
    float acc = S_o4b;
#pragma unroll
    for (int k = 0; k < 32; k++) acc = fmaf(z[k], S_o4W[k], acc);
    out[j] = sigm(acc);
}

// ---------------------------------------------------------------------------
// Launch
// ---------------------------------------------------------------------------
extern "C" void kernel_launch(void* const* d_in, const int* in_sizes, int n_in,
                              void* d_out, int out_size) {
    const float* x    = (const float*)d_in[0];
    const int*   src  = (const int*)d_in[1];
    const int*   dst  = (const int*)d_in[2];
    const int*   leaf = (const int*)d_in[3];
    const float* cmd  = (const float*)d_in[4];
    const float* p1W  = (const float*)d_in[5];
    const float* p1b  = (const float*)d_in[6];
    const float* s1W  = (const float*)d_in[7];
    const float* n1W  = (const float*)d_in[8];
    const float* b1   = (const float*)d_in[9];
    const float* p2W  = (const float*)d_in[10];
    const float* p2b  = (const float*)d_in[11];
    const float* s2W  = (const float*)d_in[12];
    const float* n2W  = (const float*)d_in[13];
    const float* b2   = (const float*)d_in[14];
    const float* cmdW = (const float*)d_in[15];
    const float* cmdb = (const float*)d_in[16];
    const float* o1W  = (const float*)d_in[17];
    const float* o1b  = (const float*)d_in[18];
    const float* o2W  = (const float*)d_in[19];
    const float* o2b  = (const float*)d_in[20];
    const float* o3W  = (const float*)d_in[21];
    const float* o3b  = (const float*)d_in[22];
    const float* o4W  = (const float*)d_in[23];
    const float* o4b  = (const float*)d_in[24];

    int N = in_sizes[0] / 5;
    int E = in_sizes[1];
    int L = in_sizes[3];

    int nb = (N + 255) / 256;
    int lb = (L + 255) / 256;
    // edge kernels: 6 edges per warp, 8 warps per block -> 48 edges/block
    int eb = (E + 47) / 48;

    node1_kernel<<<nb, 256>>>(x, p1W, p1b, N);
    leafset_kernel<<<lb, 256>>>(leaf, L);
    edge_kernel<false><<<eb, 256>>>(src, dst, E);
    node2_kernel<<<nb, 256>>>(x, s1W, n1W, b1, p2W, p2b, N);
    edge_kernel<true><<<eb, 256>>>(src, dst, E);
    leaf_kernel<<<lb, 256>>>(leaf, cmd, s2W, n2W, b2, cmdW, cmdb,
                             o1W, o1b, o2W, o2b, o3W, o3b, o4W, o4b,
                             (float*)d_out, L);
}

// round 5
// speedup vs baseline: 2.2973x; 2.2973x over previous
#include <cuda_runtime.h>

// ---------------------------------------------------------------------------
// Scratch (static __device__ globals — no allocation allowed)
// ---------------------------------------------------------------------------
#define NCAP 1000000
#define NWORDS 31250          // ceil(NCAP/32) bitmap words
#define FPAD 8                // padded feature stride (32B rows = one L2 sector)

__device__ float d_m[NCAP * FPAD];     // pool messages, stride 8 (32B-aligned rows)
__device__ float d_agg[NCAP * FPAD];   // segment-max accumulator, stride 8
__device__ float d_h1[NCAP * 5];       // sigmoid(conv1 output)
__device__ unsigned d_leafbm[NWORDS];  // leaf-node bitmap (125KB, L1-resident)

__device__ __forceinline__ float sigm(float x) {
    return 1.0f / (1.0f + __expf(-x));
}

// ---------------------------------------------------------------------------
// Kernel: m1 = relu(x @ p1_W + p1_b); agg = 0; bitmap = 0
// ---------------------------------------------------------------------------
__global__ void node1_kernel(const float* __restrict__ x,
                             const float* __restrict__ W,
                             const float* __restrict__ b,
                             int N) {
    int i = blockIdx.x * blockDim.x + threadIdx.x;
    if (i < NWORDS) d_leafbm[i] = 0u;
    if (i >= N) return;
    float xv[5], m[5];
#pragma unroll
    for (int k = 0; k < 5; k++) xv[k] = x[i * 5 + k];
#pragma unroll
    for (int f = 0; f < 5; f++) {
        float acc = b[f];
#pragma unroll
        for (int k = 0; k < 5; k++) acc = fmaf(xv[k], W[k * 5 + f], acc);
        m[f] = fmaxf(acc, 0.0f);
    }
    float4* m4 = reinterpret_cast<float4*>(d_m) + (size_t)i * 2;
    m4[0] = make_float4(m[0], m[1], m[2], m[3]);
    m4[1] = make_float4(m[4], 0.0f, 0.0f, 0.0f);
    float4 z4 = make_float4(0.0f, 0.0f, 0.0f, 0.0f);
    float4* a4 = reinterpret_cast<float4*>(d_agg) + (size_t)i * 2;
    a4[0] = z4;
    a4[1] = z4;
}

// ---------------------------------------------------------------------------
// Kernel: set leaf bits
// ---------------------------------------------------------------------------
__global__ void leafset_kernel(const int* __restrict__ leaf, int L) {
    int j = blockIdx.x * blockDim.x + threadIdx.x;
    if (j >= L) return;
    int n = leaf[j];
    atomicOr(&d_leafbm[n >> 5], 1u << (n & 31));
}

// ---------------------------------------------------------------------------
// Edge scatter-max, one edge per thread.
//   gather  : m[src]  row = exactly 1 L2 sector (float4 + scalar, 32B-aligned)
//   precheck: agg[dst] row = exactly 1 L2 sector (float4 + scalar)
//   atomic  : only for features that strictly improve (stale reads are safe:
//             agg values only grow; the atomic re-resolves the race exactly).
// relu output >= 0 so signed-int atomicMax on the float bits is exact, and
// the compare a>c with c>=0 also subsumes the zero-message skip.
// FILTER: layer 2 aggregation is only read at leaf nodes -> skip ~87% of
// edges after one bitmap probe (bitmap is L1-resident).
// ---------------------------------------------------------------------------
template <bool FILTER>
__global__ void edge_kernel(const int* __restrict__ src,
                            const int* __restrict__ dst,
                            int E) {
    int i = blockIdx.x * blockDim.x + threadIdx.x;
    if (i >= E) return;
    int d = dst[i];
    if (FILTER) {
        unsigned bm = d_leafbm[d >> 5];
        if (!((bm >> (d & 31)) & 1u)) return;
    }
    int s = src[i];
    const float4* m4 = reinterpret_cast<const float4*>(d_m) + (size_t)s * 2;
    float4 a = m4[0];
    float a4 = d_m[(size_t)s * FPAD + 4];

    const float4* g4 = reinterpret_cast<const float4*>(d_agg) + (size_t)d * 2;
    float4 c = g4[0];
    float c4 = d_agg[(size_t)d * FPAD + 4];

    int* ag = reinterpret_cast<int*>(d_agg) + (size_t)d * FPAD;
    if (a.x > c.x) atomicMax(ag + 0, __float_as_int(a.x));
    if (a.y > c.y) atomicMax(ag + 1, __float_as_int(a.y));
    if (a.z > c.z) atomicMax(ag + 2, __float_as_int(a.z));
    if (a.w > c.w) atomicMax(ag + 3, __float_as_int(a.w));
    if (a4  > c4 ) atomicMax(ag + 4, __float_as_int(a4));
}

// ---------------------------------------------------------------------------
// Kernel: h1 = sigmoid(x @ s1_W + agg1 @ n1_W + b1)
//         m2 = relu(h1 @ p2_W + p2_b); agg = 0 (reused for layer 2)
// ---------------------------------------------------------------------------
__global__ void node2_kernel(const float* __restrict__ x,
                             const float* __restrict__ s1W,
                             const float* __restrict__ n1W,
                             const float* __restrict__ b1,
                             const float* __restrict__ p2W,
                             const float* __restrict__ p2b,
                             int N) {
    int i = blockIdx.x * blockDim.x + threadIdx.x;
    if (i >= N) return;
    float xv[5], av[5], h[5], m[5];
#pragma unroll
    for (int k = 0; k < 5; k++) xv[k] = x[i * 5 + k];
    const float4* a4c = reinterpret_cast<const float4*>(d_agg) + (size_t)i * 2;
    float4 a0 = a4c[0];
    av[0] = a0.x; av[1] = a0.y; av[2] = a0.z; av[3] = a0.w;
    av[4] = d_agg[(size_t)i * FPAD + 4];
#pragma unroll
    for (int f = 0; f < 5; f++) {
        float acc = b1[f];
#pragma unroll
        for (int k = 0; k < 5; k++) acc = fmaf(xv[k], s1W[k * 5 + f], acc);
#pragma unroll
        for (int k = 0; k < 5; k++) acc = fmaf(av[k], n1W[k * 5 + f], acc);
        h[f] = sigm(acc);
        d_h1[(size_t)i * 5 + f] = h[f];
    }
#pragma unroll
    for (int f = 0; f < 5; f++) {
        float acc = p2b[f];
#pragma unroll
        for (int k = 0; k < 5; k++) acc = fmaf(h[k], p2W[k * 5 + f], acc);
        m[f] = fmaxf(acc, 0.0f);
    }
    float4* m4 = reinterpret_cast<float4*>(d_m) + (size_t)i * 2;
    m4[0] = make_float4(m[0], m[1], m[2], m[3]);
    m4[1] = make_float4(m[4], 0.0f, 0.0f, 0.0f);
    float4 z4 = make_float4(0.0f, 0.0f, 0.0f, 0.0f);
    float4* a4 = reinterpret_cast<float4*>(d_agg) + (size_t)i * 2;
    a4[0] = z4;
    a4[1] = z4;
}

// ---------------------------------------------------------------------------
// Kernel: leaf-only conv2 output + command product + 4-layer sigmoid MLP
// ---------------------------------------------------------------------------
__global__ __launch_bounds__(256) void leaf_kernel(
    const int* __restrict__ leaf, const float* __restrict__ cmd,
    const float* __restrict__ s2W, const float* __restrict__ n2W,
    const float* __restrict__ b2,
    const float* __restrict__ cmdW, const float* __restrict__ cmdb,
    const float* __restrict__ o1W, const float* __restrict__ o1b,
    const float* __restrict__ o2W, const float* __restrict__ o2b,
    const float* __restrict__ o3W, const float* __restrict__ o3b,
    const float* __restrict__ o4W, const float* __restrict__ o4b,
    float* __restrict__ out, int L) {

    __shared__ float S_s2W[50], S_n2W[50], S_b2[10], S_enc[10];
    __shared__ float S_o1W[320], S_o1b[32];
    __shared__ float S_o2W[1024], S_o2b[32];
    __shared__ float S_o3W[1024], S_o3b[32];
    __shared__ float S_o4W[32], S_o4b;

    int t = threadIdx.x;
    for (int k = t; k < 50; k += 256) { S_s2W[k] = s2W[k]; S_n2W[k] = n2W[k]; }
    for (int k = t; k < 320; k += 256) S_o1W[k] = o1W[k];
    for (int k = t; k < 1024; k += 256) { S_o2W[k] = o2W[k]; S_o3W[k] = o3W[k]; }
    if (t < 32) { S_o1b[t] = o1b[t]; S_o2b[t] = o2b[t]; S_o3b[t] = o3b[t]; S_o4W[t] = o4W[t]; }
    if (t < 10) {
        S_b2[t] = b2[t];
        S_enc[t] = cmdb[t] + cmd[0] * cmdW[t] + cmd[1] * cmdW[10 + t];
    }
    if (t == 0) S_o4b = o4b[0];
    __syncthreads();

    int j = blockIdx.x * 256 + t;
    if (j >= L) return;
    int node = leaf[j];

    float hv[5], av[5];
#pragma unroll
    for (int k = 0; k < 5; k++) hv[k] = d_h1[(size_t)node * 5 + k];
    const float4* a4c = reinterpret_cast<const float4*>(d_agg) + (size_t)node * 2;
    float4 a0 = a4c[0];
    av[0] = a0.x; av[1] = a0.y; av[2] = a0.z; av[3] = a0.w;
    av[4] = d_agg[(size_t)node * FPAD + 4];

    float p[10];
#pragma unroll
    for (int f = 0; f < 10; f++) {
        float acc = S_b2[f];
#pragma unroll
        for (int k = 0; k < 5; k++) acc = fmaf(hv[k], S_s2W[k * 10 + f], acc);
#pragma unroll
        for (int k = 0; k < 5; k++) acc = fmaf(av[k], S_n2W[k * 10 + f], acc);
        p[f] = acc * S_enc[f];
    }

    float z[32], z2[32];
#pragma unroll
    for (int f = 0; f < 32; f++) {
        float acc = S_o1b[f];
#pragma unroll
        for (int k = 0; k < 10; k++) acc = fmaf(p[k], S_o1W[k * 32 + f], acc);
        z[f] = sigm(acc);
    }
#pragma unroll
    for (int f = 0; f < 32; f++) {
        float acc = S_o2b[f];
#pragma unroll
        for (int k = 0; k < 32; k++) acc = fmaf(z[k], S_o2W[k * 32 + f], acc);
        z2[f] = sigm(acc);
    }
#pragma unroll
    for (int f = 0; f < 32; f++) {
        float acc = S_o3b[f];
#pragma unroll
        for (int k = 0; k < 32; k++) acc = fmaf(z2[k], S_o3W[k * 32 + f], acc);
        z[f] = sigm(acc);
    }
    float acc = S_o4b;
#pragma unroll
    for (int k = 0; k < 32; k++) acc = fmaf(z[k], S_o4W[k], acc);
    out[j] = sigm(acc);
}

// ---------------------------------------------------------------------------
// Launch
// ---------------------------------------------------------------------------
extern "C" void kernel_launch(void* const* d_in, const int* in_sizes, int n_in,
                              void* d_out, int out_size) {
    const float* x    = (const float*)d_in[0];
    const int*   src  = (const int*)d_in[1];
    const int*   dst  = (const int*)d_in[2];
    const int*   leaf = (const int*)d_in[3];
    const float* cmd  = (const float*)d_in[4];
    const float* p1W  = (const float*)d_in[5];
    const float* p1b  = (const float*)d_in[6];
    const float* s1W  = (const float*)d_in[7];
    const float* n1W  = (const float*)d_in[8];
    const float* b1   = (const float*)d_in[9];
    const float* p2W  = (const float*)d_in[10];
    const float* p2b  = (const float*)d_in[11];
    const float* s2W  = (const float*)d_in[12];
    const float* n2W  = (const float*)d_in[13];
    const float* b2   = (const float*)d_in[14];
    const float* cmdW = (const float*)d_in[15];
    const float* cmdb = (const float*)d_in[16];
    const float* o1W  = (const float*)d_in[17];
    const float* o1b  = (const float*)d_in[18];
    const float* o2W  = (const float*)d_in[19];
    const float* o2b  = (const float*)d_in[20];
    const float* o3W  = (const float*)d_in[21];
    const float* o3b  = (const float*)d_in[22];
    const float* o4W  = (const float*)d_in[23];
    const float* o4b  = (const float*)d_in[24];

    int N = in_sizes[0] / 5;
    int E = in_sizes[1];
    int L = in_sizes[3];

    int nb = (N + 255) / 256;
    int lb = (L + 255) / 256;
    int eb = (E + 255) / 256;

    node1_kernel<<<nb, 256>>>(x, p1W, p1b, N);
    leafset_kernel<<<lb, 256>>>(leaf, L);
    edge_kernel<false><<<eb, 256>>>(src, dst, E);
    node2_kernel<<<nb, 256>>>(x, s1W, n1W, b1, p2W, p2b, N);
    edge_kernel<true><<<eb, 256>>>(src, dst, E);
    leaf_kernel<<<lb, 256>>>(leaf, cmd, s2W, n2W, b2, cmdW, cmdb,
                             o1W, o1b, o2W, o2b, o3W, o3b, o4W, o4b,
                             (float*)d_out, L);
}